// round 17
// baseline (speedup 1.0000x reference)
#include <cuda_runtime.h>

#define B_  32
#define D_  32
#define H_  256
#define W_  256
#define K_  512
#define TT  64                     // pair-tile size
#define NT  (K_ / TT)              // 8 tiles per image
#define NPAIRS (NT * (NT + 1) / 2) // 36 (ti <= tj)
#define NBLOCKS (B_ * NPAIRS)      // 1152
#define LTHREADS 256               // 8 warps: (m-tile, n-half) = (w>>1, w&1)
#define GTHREADS 256
#define SPAD 72                    // smem row stride (floats): (8*tig+g)&31 distinct

typedef unsigned uint32;

// Scratch: gathered pred (tf32-rounded), TRANSPOSED [B][D][K], norms, tags.
__device__ float g_predT[B_ * D_ * K_];  // 2 MB
__device__ float g_ns[B_ * K_];
__device__ int   g_tag[B_ * K_];

__device__ __forceinline__ float tanh_approx(float x) {
    float y;
    asm("tanh.approx.f32 %0, %1;" : "=f"(y) : "f"(x));
    return y;
}
__device__ __forceinline__ float tf32_round(float x) {
    uint32 u;
    asm("cvt.rna.tf32.f32 %0, %1;" : "=r"(u) : "f"(x));
    return __uint_as_float(u);
}
__device__ __forceinline__ void mma_tf32(float& c0, float& c1, float& c2, float& c3,
                                         uint32 a0, uint32 a1, uint32 a2, uint32 a3,
                                         uint32 b0, uint32 b1) {
    asm("mma.sync.aligned.m16n8k8.row.col.f32.tf32.tf32.f32 "
        "{%0,%1,%2,%3}, {%4,%5,%6,%7}, {%8,%9}, {%0,%1,%2,%3};"
        : "+f"(c0), "+f"(c1), "+f"(c2), "+f"(c3)
        : "r"(a0), "r"(a1), "r"(a2), "r"(a3), "r"(b0), "r"(b1));
}

// dtype probe: int64 => high dword of every value is 0 (values < 256);
// int32 => odd dwords uniform 0..255 (false-positive prob 256^-16).
__device__ __forceinline__ bool probe_is64(const void* kpts_raw) {
    const uint32* kd = (const uint32*)kpts_raw;
    bool is64 = true;
#pragma unroll
    for (int i = 1; i < 32; i += 2) is64 &= (__ldg(kd + i) == 0u);
    return is64;
}

__device__ __forceinline__ void read_point(const void* kpts_raw,
                                           const void* tags_raw, bool is64,
                                           int pt, int& r, int& c, int& tg) {
    if (is64) {
        const long long* kp  = (const long long*)kpts_raw;
        const long long* tgp = (const long long*)tags_raw;
        r  = (int)kp[(size_t)pt * 2 + 0];
        c  = (int)kp[(size_t)pt * 2 + 1];
        tg = (int)tgp[pt];
    } else {
        const int* kp  = (const int*)kpts_raw;
        const int* tgp = (const int*)tags_raw;
        r  = kp[(size_t)pt * 2 + 0];
        c  = kp[(size_t)pt * 2 + 1];
        tg = tgp[pt];
    }
    r = min(max(r, 0), H_ - 1);   // defensive: fail rel_err, not a crash
    c = min(max(c, 0), W_ - 1);
}

// Gather: 4 threads/point, 8 independent channel LDGs each (MLP=8).
// Stores tf32-ROUNDED values; ||p||^2 computed from the rounded values so
// the Gram diagonal identity (expo_kk ~ 0) is preserved under tf32 MMA.
__global__ void gather_kernel(const float* __restrict__ ebd,
                              const void* __restrict__ kpts_raw,
                              const void* __restrict__ tags_raw,
                              float* __restrict__ out) {
    if (blockIdx.x == 0 && threadIdx.x == 0) out[0] = 0.0f;

    int tid = blockIdx.x * blockDim.x + threadIdx.x;   // 4*(b*K + k) + h
    if (tid >= B_ * K_ * 4) return;
    int idx = tid >> 2;            // point index b*K + k
    int h   = tid & 3;             // d-quarter

    bool is64 = probe_is64(kpts_raw);
    int r, c, tg;
    read_point(kpts_raw, tags_raw, is64, idx, r, c, tg);

    int b = idx >> 9;
    int k = idx & (K_ - 1);
    const int d0 = h * (D_ / 4);
    const float* base = ebd + (size_t)b * D_ * H_ * W_ + (size_t)d0 * (H_ * W_)
                            + (size_t)r * W_ + (size_t)c;
    float* dstT = g_predT + (size_t)b * D_ * K_ + (size_t)d0 * K_ + k;
    float ns = 0.0f;
#pragma unroll
    for (int d = 0; d < D_ / 4; ++d) {
        float x = tf32_round(base[(size_t)d * (H_ * W_)]);
        dstT[(size_t)d * K_] = x;
        ns += x * x;
    }
    ns += __shfl_xor_sync(0xffffffffu, ns, 1);
    ns += __shfl_xor_sync(0xffffffffu, ns, 2);
    if (h == 0) {
        g_ns[idx]  = ns;
        g_tag[idx] = tg;
    }
}

// Symmetry-halved pairwise loss via tf32 mma.sync.m16n8k8, 8 warps/block.
// Warp w: m-tile mt = w>>1 (k rows mt*16..mt*16+15),
//         n-half nh = w&1 (l cols nh*32..nh*32+31, n-tiles 4nh..4nh+3).
// Gram C[k][l] = sum_d P[d][k] * P[d][l]:  m = k-row, n = l-col, red = d.
// Fragment maps (lane = 4*g + tig):
//   a0=A[g][tig]  a1=A[g+8][tig]  a2=A[g][tig+4]  a3=A[g+8][tig+4]
//   b0=B[tig][n=g]  b1=B[tig+4][n=g]
//   c0=C[g][2tig] c1=C[g][2tig+1] c2=C[g+8][2tig] c3=C[g+8][2tig+1]
// SPAD=72 row stride -> all fragment LDS are 32-bank conflict-free.
// psim = 2/(1+exp(x)) = 1 - tanh(x/2)  ->  e = tanh(arg) - neq.
__global__ __launch_bounds__(LTHREADS, 5) void loss_kernel(float* __restrict__ out) {
    const int b = blockIdx.x / NPAIRS;
    int p = blockIdx.x % NPAIRS;
    int ti = 0;
    while (p >= NT - ti) { p -= (NT - ti); ++ti; }
    const int tj = ti + p;

    __shared__ float sI[D_ * SPAD];   // [d][k], padded  (9216 B)
    __shared__ float sJ[D_ * SPAD];   // [d][l], padded  (9216 B)
    __shared__ float nsI[TT], nsJ[TT];
    __shared__ int   tgI[TT], tgJ[TT];
    __shared__ float wsum[LTHREADS / 32];

    const int t = threadIdx.x;
    const float* srcI = g_predT + (size_t)b * D_ * K_ + ti * TT;
    const float* srcJ = g_predT + (size_t)b * D_ * K_ + tj * TT;

    // Fill: 512 float4 per tile, 2 per thread per tile.
#pragma unroll
    for (int rr = 0; rr < 2; ++rr) {
        int idx4 = t + rr * LTHREADS;     // 0..511
        int d  = idx4 >> 4;
        int j4 = idx4 & 15;
        float4 vi = *(const float4*)(srcI + (size_t)d * K_ + j4 * 4);
        float4 vj = *(const float4*)(srcJ + (size_t)d * K_ + j4 * 4);
        *(float4*)(sI + d * SPAD + j4 * 4) = vi;
        *(float4*)(sJ + d * SPAD + j4 * 4) = vj;
    }
    {
        const int baseI = b * K_ + ti * TT;
        const int baseJ = b * K_ + tj * TT;
        if (t < TT) {
            nsI[t] = g_ns[baseI + t];    tgI[t] = g_tag[baseI + t];
        } else if (t < 2 * TT) {
            nsJ[t - TT] = g_ns[baseJ + t - TT];
            tgJ[t - TT] = g_tag[baseJ + t - TT];
        }
    }
    __syncthreads();

    const int warp = t >> 5;
    const int lane = t & 31;
    const int g    = lane >> 2;        // 0..7
    const int tig  = lane & 3;         // 0..3
    const int kw   = (warp >> 1) * 16; // k-row base of this warp
    const int nh   = warp & 1;         // n-half: n-tiles 4nh..4nh+3

    float c[4][4];
#pragma unroll
    for (int j = 0; j < 4; ++j)
#pragma unroll
        for (int i = 0; i < 4; ++i) c[j][i] = 0.0f;

#pragma unroll
    for (int ds = 0; ds < 4; ++ds) {
        const uint32* rA0 = (const uint32*)(sI + (8 * ds + tig) * SPAD);
        const uint32* rA4 = (const uint32*)(sI + (8 * ds + tig + 4) * SPAD);
        uint32 a0 = rA0[kw + g];
        uint32 a1 = rA0[kw + g + 8];
        uint32 a2 = rA4[kw + g];
        uint32 a3 = rA4[kw + g + 8];
        const uint32* rB0 = (const uint32*)(sJ + (8 * ds + tig) * SPAD);
        const uint32* rB4 = (const uint32*)(sJ + (8 * ds + tig + 4) * SPAD);
#pragma unroll
        for (int j = 0; j < 4; ++j) {
            int nt = 4 * nh + j;
            uint32 b0 = rB0[8 * nt + g];
            uint32 b1 = rB4[8 * nt + g];
            mma_tf32(c[j][0], c[j][1], c[j][2], c[j][3],
                     a0, a1, a2, a3, b0, b1);
        }
    }

    // Epilogue: 16 pairs per thread.
    // k rows: kw+g, kw+g+8; l cols per j: 8(4nh+j)+2tig, +1.
    const float nk0 = nsI[kw + g]     * (1.0f / 64.0f);
    const float nk1 = nsI[kw + g + 8] * (1.0f / 64.0f);
    const int   tk0 = tgI[kw + g];
    const int   tk1 = tgI[kw + g + 8];

    float lsum = 0.0f;
#pragma unroll
    for (int j = 0; j < 4; ++j) {
        int l0 = 8 * (4 * nh + j) + 2 * tig;
        int l1 = l0 + 1;
        float nl0 = nsJ[l0] * (1.0f / 64.0f);
        float nl1 = nsJ[l1] * (1.0f / 64.0f);
        int   tl0 = tgJ[l0];
        int   tl1 = tgJ[l1];

        float a00 = fmaf(c[j][0], -1.0f / 32.0f, nk0 + nl0);
        float a01 = fmaf(c[j][1], -1.0f / 32.0f, nk0 + nl1);
        float a10 = fmaf(c[j][2], -1.0f / 32.0f, nk1 + nl0);
        float a11 = fmaf(c[j][3], -1.0f / 32.0f, nk1 + nl1);
        float e00 = tanh_approx(a00) - ((tk0 != tl0) ? 1.0f : 0.0f);
        float e01 = tanh_approx(a01) - ((tk0 != tl1) ? 1.0f : 0.0f);
        float e10 = tanh_approx(a10) - ((tk1 != tl0) ? 1.0f : 0.0f);
        float e11 = tanh_approx(a11) - ((tk1 != tl1) ? 1.0f : 0.0f);
        lsum += e00 * e00 + e01 * e01 + e10 * e10 + e11 * e11;
    }

    // Block reduction (8 warps) + weighted atomic.
#pragma unroll
    for (int o = 16; o > 0; o >>= 1)
        lsum += __shfl_down_sync(0xffffffffu, lsum, o);
    if ((t & 31) == 0) wsum[t >> 5] = lsum;
    __syncthreads();
    if (t < LTHREADS / 32) {
        float s = wsum[t];
#pragma unroll
        for (int o = (LTHREADS / 64); o > 0; o >>= 1)
            s += __shfl_down_sync(0xffu, s, o);
        if (t == 0) {
            float w = (ti == tj) ? 1.0f : 2.0f;
            atomicAdd(out, s * w * (1.0f / ((float)B_ * (float)K_ * (float)K_)));
        }
    }
}

extern "C" void kernel_launch(void* const* d_in, const int* in_sizes, int n_in,
                              void* d_out, int out_size) {
    const float* ebd  = (const float*)d_in[0];
    const void*  kpts = (const void*)d_in[1];
    const void*  tags = (const void*)d_in[2];
    float* out = (float*)d_out;

    (void)in_sizes; (void)n_in; (void)out_size;

    gather_kernel<<<(B_ * K_ * 4 + GTHREADS - 1) / GTHREADS, GTHREADS>>>(
        ebd, kpts, tags, out);
    loss_kernel<<<NBLOCKS, LTHREADS>>>(out);
}